// round 11
// baseline (speedup 1.0000x reference)
#include <cuda_runtime.h>
#include <math.h>

// Problem constants
#define NB   2
#define NS   2048
#define NH   16
#define ND   64
#define NHID 1024
#define NCK  64      // chunk size
#define NNC  32      // chunks per sequence
#define NBH  32      // NB*NH
#define PST  68      // padded smem row stride (floats)

// Scratch (static device globals -- no allocation allowed)
__device__ float4 g_tab[NS * 32];              // xPos table: (cos*sc, sin*sc, cos/sc, sin/sc)
__device__ float  g_qr[NBH * NS * ND];         // rotated Q, [bh][s][d]
__device__ float  g_kr[NBH * NS * ND];         // rotated K, [bh][s][d]
__device__ float  g_A [NBH * NNC * ND * ND];   // per-chunk state contributions
__device__ float  g_St[NBH * NNC * ND * ND];   // prefix-scanned states (state BEFORE chunk c)

__device__ __forceinline__ double head_lg(int h) {
    const double L0 = -3.4657359027997265;   // log(1/32)
    const double L1 = -6.2383246250395075;   // log(1/512)
    double g = 1.0 - exp(L0 + (L1 - L0) * ((double)h / 15.0));
    return log(g);
}

// ---------------------------------------------------------------------------
// Kernel 0: xPos table. tab[s][i] = (cos*sc, sin*sc, cos/sc, sin/sc)
// ---------------------------------------------------------------------------
__global__ __launch_bounds__(256)
void table_kernel() {
    int idx = blockIdx.x * 256 + threadIdx.x;   // [0, 2048*32)
    int i = idx & 31;
    int s = idx >> 5;
    float invf = (float)(1.0 / pow(10000.0, (double)i / 32.0));
    float bs   = (2.0f * (float)i + 25.6f) / 89.6f;   // (2i + 0.4*64)/(1.4*64)
    float pos  = (float)s;
    float sn, cs;
    sincosf(pos * invf, &sn, &cs);
    float sc = powf(bs, pos * (1.0f / 512.0f));
    float iv = 1.0f / sc;
    g_tab[idx] = make_float4(cs * sc, sn * sc, cs * iv, sn * iv);
}

// ---------------------------------------------------------------------------
// Kernel 0.5: rope_lite -- rotation via table, zero transcendentals, coalesced.
// ---------------------------------------------------------------------------
__global__ __launch_bounds__(256)
void rope_lite_kernel(const float* __restrict__ Q, const float* __restrict__ K) {
    int idx = blockIdx.x * 256 + threadIdx.x;  // [0, NBH*NS*32)
    int i  = idx & 31;
    int s  = (idx >> 5) & (NS - 1);
    int bh = idx >> 16;
    int h  = bh & (NH - 1);
    int b  = bh >> 4;

    float4 t = g_tab[(s << 5) + i];            // (cos*sc, sin*sc, cos/sc, sin/sc)

    int gin = (b * NS + s) * NHID + h * ND + 2 * i;
    float2 q = *(const float2*)(Q + gin);
    float2 k = *(const float2*)(K + gin);

    int gout = (bh * NS + s) * ND + 2 * i;
    float2 qo, ko;
    qo.x = q.x * t.x - q.y * t.y;
    qo.y = q.y * t.x + q.x * t.y;
    ko.x = k.x * t.z - k.y * t.w;
    ko.y = k.y * t.z + k.x * t.w;
    *(float2*)(g_qr + gout) = qo;
    *(float2*)(g_kr + gout) = ko;
}

// ---------------------------------------------------------------------------
// Kernel 1: A_c[d][e] = sum_j gamma^(C-j) k'[j][d] v[j][e]
// Staging vectorized to float4 (4 passes); GEMM body unchanged (proven).
// ---------------------------------------------------------------------------
__global__ __launch_bounds__(256)
void passA_kernel(const float* __restrict__ V) {
    __shared__ float ks[NCK * PST];
    __shared__ float vs[NCK * PST];
    __shared__ float wr[NCK];

    int c = blockIdx.x, h = blockIdx.y, b = blockIdx.z;
    int bh = b * NH + h;
    int tid = threadIdx.x;

    if (tid < NCK) {
        double lg = head_lg(h);
        wr[tid] = (float)exp(lg * (double)(NCK - tid));   // gamma^(C-j)
    }
    __syncthreads();

    int c0 = c * NCK;
    const float* kg = g_kr + (bh * NS + c0) * ND;
    const float* vg = V + (b * NS + c0) * NHID + h * ND;

#pragma unroll
    for (int t = 0; t < 4; ++t) {
        int idx = t * 1024 + tid * 4;
        int r = idx >> 6, d = idx & 63;
        float4 kv = *(const float4*)(kg + r * ND + d);
        float4 vv = *(const float4*)(vg + r * NHID + d);
        float w = wr[r];
        kv.x *= w; kv.y *= w; kv.z *= w; kv.w *= w;
        *(float4*)(ks + r * PST + d) = kv;
        *(float4*)(vs + r * PST + d) = vv;
    }
    __syncthreads();

    int ty = tid >> 4, tx = tid & 15;
    float acc[4][4];
#pragma unroll
    for (int di = 0; di < 4; ++di)
#pragma unroll
        for (int ei = 0; ei < 4; ++ei) acc[di][ei] = 0.0f;

#pragma unroll 8
    for (int j = 0; j < NCK; ++j) {
        float a0 = ks[j * PST + 4 * ty + 0];
        float a1 = ks[j * PST + 4 * ty + 1];
        float a2 = ks[j * PST + 4 * ty + 2];
        float a3 = ks[j * PST + 4 * ty + 3];
        float4 bv = *(const float4*)(vs + j * PST + 4 * tx);
        acc[0][0] += a0 * bv.x; acc[0][1] += a0 * bv.y; acc[0][2] += a0 * bv.z; acc[0][3] += a0 * bv.w;
        acc[1][0] += a1 * bv.x; acc[1][1] += a1 * bv.y; acc[1][2] += a1 * bv.z; acc[1][3] += a1 * bv.w;
        acc[2][0] += a2 * bv.x; acc[2][1] += a2 * bv.y; acc[2][2] += a2 * bv.z; acc[2][3] += a2 * bv.w;
        acc[3][0] += a3 * bv.x; acc[3][1] += a3 * bv.y; acc[3][2] += a3 * bv.z; acc[3][3] += a3 * bv.w;
    }

    float* ag = g_A + ((size_t)bh * NNC + c) * ND * ND;
#pragma unroll
    for (int di = 0; di < 4; ++di) {
        float4 w = make_float4(acc[di][0], acc[di][1], acc[di][2], acc[di][3]);
        *(float4*)&ag[(4 * ty + di) * ND + 4 * tx] = w;
    }
}

// ---------------------------------------------------------------------------
// Kernel 2: prefix scan v3 -- 256 CTAs (1/8 plane each, float2/thread),
// depth-8 prefetch. More CTAs/SM -> more outstanding loads -> BW floor.
// ---------------------------------------------------------------------------
__global__ __launch_bounds__(256)
void scan_kernel() {
    int blk = blockIdx.x;          // NBH*8 = 256
    int bh = blk >> 3;
    int part = blk & 7;
    int h = bh & (NH - 1);
    int tid = threadIdx.x;
    double lg = head_lg(h);
    float dec = (float)exp(lg * (double)NCK);

    size_t base = (size_t)bh * NNC * ND * ND + part * 512 + tid * 2;

    float2 buf[8];
#pragma unroll
    for (int p = 0; p < 8; ++p)
        buf[p] = *(const float2*)(g_A + base + (size_t)p * ND * ND);

    float2 st = make_float2(0.f, 0.f);
#pragma unroll
    for (int c = 0; c < NNC; ++c) {
        *(float2*)(g_St + base + (size_t)c * ND * ND) = st;
        float2 a = buf[c & 7];
        if (c + 8 < NNC)
            buf[c & 7] = *(const float2*)(g_A + base + (size_t)(c + 8) * ND * ND);
        st.x = st.x * dec + a.x;
        st.y = st.y * dec + a.y;
    }
}

// ---------------------------------------------------------------------------
// Kernel 3: per-chunk output. GEMM bodies unchanged (proven, 4 CTAs/SM);
// staging vectorized to float4 (incl. St restage).
// ---------------------------------------------------------------------------
extern __shared__ float smC[];

__global__ __launch_bounds__(256, 4)
void passC_kernel(const float* __restrict__ V, float* __restrict__ out) {
    float* qs  = smC;                            // [i][d]  NCK*PST
    float* ksT = smC + NCK * PST;                // [d][j] swizzled; reused as ps[i][j]
    float* vs  = smC + NCK * PST + NCK * NCK;    // [j][e]; reused as sts[d'][e]
    float* wq  = vs + NCK * PST;                 // [NCK] gamma^i
    float* wk  = wq + NCK;                       // [NCK] gamma^{-j}

    int c = blockIdx.x, h = blockIdx.y, b = blockIdx.z;
    int bh = b * NH + h;
    int tid = threadIdx.x;
    int c0 = c * NCK;

    if (tid < NCK) {
        double lg = head_lg(h);
        wq[tid] = (float)exp(lg * (double)tid);
        wk[tid] = (float)exp(-lg * (double)tid);
    }
    __syncthreads();

    const float* qg = g_qr + (bh * NS + c0) * ND;
    const float* kg = g_kr + (bh * NS + c0) * ND;
    const float* vg = V + (b * NS + c0) * NHID + h * ND;

#pragma unroll
    for (int t = 0; t < 4; ++t) {
        int idx = t * 1024 + tid * 4;
        int r = idx >> 6, d = idx & 63;
        float4 qv = *(const float4*)(qg + r * ND + d);
        float4 kv = *(const float4*)(kg + r * ND + d);
        float4 vv = *(const float4*)(vg + r * NHID + d);
        float wqr = wq[r], wkr = wk[r];
        qv.x *= wqr; qv.y *= wqr; qv.z *= wqr; qv.w *= wqr;
        *(float4*)(qs + r * PST + d) = qv;
        // transpose + xor swizzle for K'
        int rh = r >> 2, rl = r & 3;
        ksT[(d + 0) * NCK + ((rh ^ ((d + 0) & 15)) << 2) + rl] = kv.x * wkr;
        ksT[(d + 1) * NCK + ((rh ^ ((d + 1) & 15)) << 2) + rl] = kv.y * wkr;
        ksT[(d + 2) * NCK + ((rh ^ ((d + 2) & 15)) << 2) + rl] = kv.z * wkr;
        ksT[(d + 3) * NCK + ((rh ^ ((d + 3) & 15)) << 2) + rl] = kv.w * wkr;
        *(float4*)(vs + r * PST + d) = vv;
    }
    __syncthreads();

    int ty = tid >> 4, tx = tid & 15;
    int i0 = 4 * ty, j0 = 4 * tx;

    // ---- GEMM1: P = Q'.K'^T ----
    float acc[4][4];
#pragma unroll
    for (int di = 0; di < 4; ++di)
#pragma unroll
        for (int ei = 0; ei < 4; ++ei) acc[di][ei] = 0.0f;

#pragma unroll 8
    for (int d = 0; d < ND; ++d) {
        float a0 = qs[(i0 + 0) * PST + d];
        float a1 = qs[(i0 + 1) * PST + d];
        float a2 = qs[(i0 + 2) * PST + d];
        float a3 = qs[(i0 + 3) * PST + d];
        float4 bv = *(const float4*)&ksT[d * NCK + ((tx ^ (d & 15)) << 2)];
        acc[0][0] += a0 * bv.x; acc[0][1] += a0 * bv.y; acc[0][2] += a0 * bv.z; acc[0][3] += a0 * bv.w;
        acc[1][0] += a1 * bv.x; acc[1][1] += a1 * bv.y; acc[1][2] += a1 * bv.z; acc[1][3] += a1 * bv.w;
        acc[2][0] += a2 * bv.x; acc[2][1] += a2 * bv.y; acc[2][2] += a2 * bv.z; acc[2][3] += a2 * bv.w;
        acc[3][0] += a3 * bv.x; acc[3][1] += a3 * bv.y; acc[3][2] += a3 * bv.z; acc[3][3] += a3 * bv.w;
    }
    __syncthreads();   // done reading ksT

    // ---- mask + stage P into ksT's space ----
    float* ps = ksT;
#pragma unroll
    for (int di = 0; di < 4; ++di) {
        int ii = i0 + di;
        float4 w;
        w.x = (j0 + 0 <= ii) ? acc[di][0] : 0.0f;
        w.y = (j0 + 1 <= ii) ? acc[di][1] : 0.0f;
        w.z = (j0 + 2 <= ii) ? acc[di][2] : 0.0f;
        w.w = (j0 + 3 <= ii) ? acc[di][3] : 0.0f;
        *(float4*)&ps[ii * NCK + j0] = w;
    }
    __syncthreads();

    // ---- GEMM2a: O = P.V ----
    float o[4][4];
#pragma unroll
    for (int di = 0; di < 4; ++di)
#pragma unroll
        for (int ei = 0; ei < 4; ++ei) o[di][ei] = 0.0f;

#pragma unroll 8
    for (int j = 0; j < NCK; ++j) {
        float a0 = ps[(i0 + 0) * NCK + j];
        float a1 = ps[(i0 + 1) * NCK + j];
        float a2 = ps[(i0 + 2) * NCK + j];
        float a3 = ps[(i0 + 3) * NCK + j];
        float4 bv = *(const float4*)(vs + j * PST + j0);
        o[0][0] += a0 * bv.x; o[0][1] += a0 * bv.y; o[0][2] += a0 * bv.z; o[0][3] += a0 * bv.w;
        o[1][0] += a1 * bv.x; o[1][1] += a1 * bv.y; o[1][2] += a1 * bv.z; o[1][3] += a1 * bv.w;
        o[2][0] += a2 * bv.x; o[2][1] += a2 * bv.y; o[2][2] += a2 * bv.z; o[2][3] += a2 * bv.w;
        o[3][0] += a3 * bv.x; o[3][1] += a3 * bv.y; o[3][2] += a3 * bv.z; o[3][3] += a3 * bv.w;
    }
    __syncthreads();   // done reading vs

    // ---- stage St over vs (float4) ----
    {
        const float* stg = g_St + ((size_t)bh * NNC + c) * ND * ND;
#pragma unroll
        for (int t = 0; t < 4; ++t) {
            int idx = t * 1024 + tid * 4;
            int r = idx >> 6, e = idx & 63;
            *(float4*)(vs + r * PST + e) = *(const float4*)(stg + idx);
        }
    }
    __syncthreads();

    // ---- GEMM2b: O += Q'.St ----
    float* sts = vs;
#pragma unroll 8
    for (int d = 0; d < ND; ++d) {
        float a0 = qs[(i0 + 0) * PST + d];
        float a1 = qs[(i0 + 1) * PST + d];
        float a2 = qs[(i0 + 2) * PST + d];
        float a3 = qs[(i0 + 3) * PST + d];
        float4 bv = *(const float4*)(sts + d * PST + j0);
        o[0][0] += a0 * bv.x; o[0][1] += a0 * bv.y; o[0][2] += a0 * bv.z; o[0][3] += a0 * bv.w;
        o[1][0] += a1 * bv.x; o[1][1] += a1 * bv.y; o[1][2] += a1 * bv.z; o[1][3] += a1 * bv.w;
        o[2][0] += a2 * bv.x; o[2][1] += a2 * bv.y; o[2][2] += a2 * bv.z; o[2][3] += a2 * bv.w;
        o[3][0] += a3 * bv.x; o[3][1] += a3 * bv.y; o[3][2] += a3 * bv.z; o[3][3] += a3 * bv.w;
    }

    float* og = out + ((size_t)(b * NS + c0)) * NHID + h * ND;
#pragma unroll
    for (int di = 0; di < 4; ++di) {
        float4 w = make_float4(o[di][0], o[di][1], o[di][2], o[di][3]);
        *(float4*)&og[(size_t)(i0 + di) * NHID + j0] = w;
    }
}

// ---------------------------------------------------------------------------
extern "C" void kernel_launch(void* const* d_in, const int* in_sizes, int n_in,
                              void* d_out, int out_size) {
    (void)in_sizes; (void)n_in; (void)out_size;
    const float* Q = (const float*)d_in[0];
    const float* K = (const float*)d_in[1];
    const float* V = (const float*)d_in[2];
    float* out = (float*)d_out;

    table_kernel<<<(NS * 32) / 256, 256>>>();
    rope_lite_kernel<<<(NBH * NS * 32) / 256, 256>>>(Q, K);

    dim3 grid(NNC, NH, NB);
    passA_kernel<<<grid, 256>>>(V);
    scan_kernel<<<NBH * 8, 256>>>();

    size_t shm = (size_t)(2 * NCK * PST + NCK * NCK + 2 * NCK) * sizeof(float);  // 51712 B
    cudaFuncSetAttribute(passC_kernel, cudaFuncAttributeMaxDynamicSharedMemorySize, (int)shm);
    passC_kernel<<<grid, 256, shm>>>(V, out);
}

// round 12
// speedup vs baseline: 1.3898x; 1.3898x over previous
#include <cuda_runtime.h>
#include <math.h>

// Problem constants
#define NB   2
#define NS   2048
#define NH   16
#define ND   64
#define NHID 1024
#define NCK  64      // chunk size
#define NNC  32      // chunks per sequence
#define NBH  32      // NB*NH
#define PST  68      // padded smem row stride (floats)

// Scratch (static device globals -- no allocation allowed)
__device__ float4 g_tab[NS * 32];              // xPos table: (cos*sc, sin*sc, cos/sc, sin/sc)
__device__ float  g_qr[NBH * NS * ND];         // rotated Q, [bh][s][d]
__device__ float  g_kr[NBH * NS * ND];         // rotated K, [bh][s][d]
__device__ float  g_A [NBH * NNC * ND * ND];   // per-chunk state contributions
__device__ float  g_St[NBH * NNC * ND * ND];   // prefix-scanned states (state BEFORE chunk c)

__device__ __forceinline__ double head_lg(int h) {
    const double L0 = -3.4657359027997265;   // log(1/32)
    const double L1 = -6.2383246250395075;   // log(1/512)
    double g = 1.0 - exp(L0 + (L1 - L0) * ((double)h / 15.0));
    return log(g);
}

// ---------------------------------------------------------------------------
// Kernel 0: xPos table. tab[s][i] = (cos*sc, sin*sc, cos/sc, sin/sc)
// ---------------------------------------------------------------------------
__global__ __launch_bounds__(256)
void table_kernel() {
    int idx = blockIdx.x * 256 + threadIdx.x;   // [0, 2048*32)
    int i = idx & 31;
    int s = idx >> 5;
    float invf = (float)(1.0 / pow(10000.0, (double)i / 32.0));
    float bs   = (2.0f * (float)i + 25.6f) / 89.6f;   // (2i + 0.4*64)/(1.4*64)
    float pos  = (float)s;
    float sn, cs;
    sincosf(pos * invf, &sn, &cs);
    float sc = powf(bs, pos * (1.0f / 512.0f));
    float iv = 1.0f / sc;
    g_tab[idx] = make_float4(cs * sc, sn * sc, cs * iv, sn * iv);
}

// ---------------------------------------------------------------------------
// Kernel 0.5: rope_lite v2 -- 4 floats per thread (float4 in/out), table-based.
// ---------------------------------------------------------------------------
__global__ __launch_bounds__(256)
void rope_lite_kernel(const float* __restrict__ Q, const float* __restrict__ K) {
    int idx = blockIdx.x * 256 + threadIdx.x;  // [0, NBH*NS*16)
    int iq = idx & 15;                          // quad index, d0 = 4*iq
    int s  = (idx >> 4) & (NS - 1);
    int bh = idx >> 15;
    int h  = bh & (NH - 1);
    int b  = bh >> 4;
    int d0 = 4 * iq;

    float4 t0 = g_tab[(s << 5) + 2 * iq];      // pairs 2iq, 2iq+1
    float4 t1 = g_tab[(s << 5) + 2 * iq + 1];

    int gin = (b * NS + s) * NHID + h * ND + d0;
    float4 q = *(const float4*)(Q + gin);
    float4 k = *(const float4*)(K + gin);

    float4 qo, ko;
    qo.x = q.x * t0.x - q.y * t0.y;
    qo.y = q.y * t0.x + q.x * t0.y;
    qo.z = q.z * t1.x - q.w * t1.y;
    qo.w = q.w * t1.x + q.z * t1.y;
    ko.x = k.x * t0.z - k.y * t0.w;
    ko.y = k.y * t0.z + k.x * t0.w;
    ko.z = k.z * t1.z - k.w * t1.w;
    ko.w = k.w * t1.z + k.z * t1.w;

    int gout = (bh * NS + s) * ND + d0;
    *(float4*)(g_qr + gout) = qo;
    *(float4*)(g_kr + gout) = ko;
}

// ---------------------------------------------------------------------------
// Kernel 1: A_c[d][e] = sum_j gamma^(C-j) k'[j][d] v[j][e]   (Round-10 proven)
// ---------------------------------------------------------------------------
__global__ __launch_bounds__(256)
void passA_kernel(const float* __restrict__ V) {
    __shared__ float ks[NCK * PST];
    __shared__ float vs[NCK * PST];
    __shared__ float wr[NCK];

    int c = blockIdx.x, h = blockIdx.y, b = blockIdx.z;
    int bh = b * NH + h;
    int tid = threadIdx.x;

    if (tid < NCK) {
        double lg = head_lg(h);
        wr[tid] = (float)exp(lg * (double)(NCK - tid));   // gamma^(C-j)
    }
    __syncthreads();

    int c0 = c * NCK;
    const float* kg = g_kr + (bh * NS + c0) * ND;
    const float* vg = V + (b * NS + c0) * NHID + h * ND;

#pragma unroll
    for (int t = 0; t < 16; ++t) {
        int idx = tid + t * 256;
        int r = idx >> 6, d = idx & 63;
        ks[r * PST + d] = kg[r * ND + d] * wr[r];
        vs[r * PST + d] = vg[r * NHID + d];
    }
    __syncthreads();

    int ty = tid >> 4, tx = tid & 15;
    float acc[4][4];
#pragma unroll
    for (int di = 0; di < 4; ++di)
#pragma unroll
        for (int ei = 0; ei < 4; ++ei) acc[di][ei] = 0.0f;

#pragma unroll 8
    for (int j = 0; j < NCK; ++j) {
        float a0 = ks[j * PST + 4 * ty + 0];
        float a1 = ks[j * PST + 4 * ty + 1];
        float a2 = ks[j * PST + 4 * ty + 2];
        float a3 = ks[j * PST + 4 * ty + 3];
        float4 bv = *(const float4*)(vs + j * PST + 4 * tx);
        acc[0][0] += a0 * bv.x; acc[0][1] += a0 * bv.y; acc[0][2] += a0 * bv.z; acc[0][3] += a0 * bv.w;
        acc[1][0] += a1 * bv.x; acc[1][1] += a1 * bv.y; acc[1][2] += a1 * bv.z; acc[1][3] += a1 * bv.w;
        acc[2][0] += a2 * bv.x; acc[2][1] += a2 * bv.y; acc[2][2] += a2 * bv.z; acc[2][3] += a2 * bv.w;
        acc[3][0] += a3 * bv.x; acc[3][1] += a3 * bv.y; acc[3][2] += a3 * bv.z; acc[3][3] += a3 * bv.w;
    }

    float* ag = g_A + ((size_t)bh * NNC + c) * ND * ND;
#pragma unroll
    for (int di = 0; di < 4; ++di) {
        float4 w = make_float4(acc[di][0], acc[di][1], acc[di][2], acc[di][3]);
        *(float4*)&ag[(4 * ty + di) * ND + 4 * tx] = w;
    }
}

// ---------------------------------------------------------------------------
// Kernel 2: gather-scan. One thread per (bh, element); 32 INDEPENDENT
// coalesced loads (MLP=32), register scan (31 FMAs), 32 coalesced stores.
// Bandwidth-bound by construction, no latency exposure.
// ---------------------------------------------------------------------------
__global__ __launch_bounds__(256)
void scan_kernel() {
    int gidx = blockIdx.x * 256 + threadIdx.x;   // [0, NBH*4096)
    int bh = gidx >> 12;
    int elem = gidx & 4095;
    int h = bh & (NH - 1);
    double lg = head_lg(h);
    float dec = (float)exp(lg * (double)NCK);

    size_t base = (size_t)bh * NNC * ND * ND + elem;

    float a[NNC];
#pragma unroll
    for (int c = 0; c < NNC; ++c)
        a[c] = g_A[base + (size_t)c * ND * ND];

    float st = 0.0f;
#pragma unroll
    for (int c = 0; c < NNC; ++c) {
        g_St[base + (size_t)c * ND * ND] = st;
        st = st * dec + a[c];
    }
}

// ---------------------------------------------------------------------------
// Kernel 3: per-chunk output (Round-10 proven, 4 CTAs/SM).
// ---------------------------------------------------------------------------
extern __shared__ float smC[];

__global__ __launch_bounds__(256, 4)
void passC_kernel(const float* __restrict__ V, float* __restrict__ out) {
    float* qs  = smC;                            // [i][d]  NCK*PST
    float* ksT = smC + NCK * PST;                // [d][j] swizzled; reused as ps[i][j]
    float* vs  = smC + NCK * PST + NCK * NCK;    // [j][e]; reused as sts[d'][e]
    float* wq  = vs + NCK * PST;                 // [NCK] gamma^i
    float* wk  = wq + NCK;                       // [NCK] gamma^{-j}

    int c = blockIdx.x, h = blockIdx.y, b = blockIdx.z;
    int bh = b * NH + h;
    int tid = threadIdx.x;
    int c0 = c * NCK;

    if (tid < NCK) {
        double lg = head_lg(h);
        wq[tid] = (float)exp(lg * (double)tid);
        wk[tid] = (float)exp(-lg * (double)tid);
    }
    __syncthreads();

    const float* qg = g_qr + (bh * NS + c0) * ND;
    const float* kg = g_kr + (bh * NS + c0) * ND;
    const float* vg = V + (b * NS + c0) * NHID + h * ND;

#pragma unroll
    for (int t = 0; t < 16; ++t) {
        int idx = tid + t * 256;
        int r = idx >> 6, d = idx & 63;
        qs[r * PST + d] = qg[r * ND + d] * wq[r];
        float kv = kg[r * ND + d] * wk[r];
        ksT[d * NCK + (((r >> 2) ^ (d & 15)) << 2) + (r & 3)] = kv;
        vs[r * PST + d] = vg[r * NHID + d];
    }
    __syncthreads();

    int ty = tid >> 4, tx = tid & 15;
    int i0 = 4 * ty, j0 = 4 * tx;

    // ---- GEMM1: P = Q'.K'^T ----
    float acc[4][4];
#pragma unroll
    for (int di = 0; di < 4; ++di)
#pragma unroll
        for (int ei = 0; ei < 4; ++ei) acc[di][ei] = 0.0f;

#pragma unroll 8
    for (int d = 0; d < ND; ++d) {
        float a0 = qs[(i0 + 0) * PST + d];
        float a1 = qs[(i0 + 1) * PST + d];
        float a2 = qs[(i0 + 2) * PST + d];
        float a3 = qs[(i0 + 3) * PST + d];
        float4 bv = *(const float4*)&ksT[d * NCK + ((tx ^ (d & 15)) << 2)];
        acc[0][0] += a0 * bv.x; acc[0][1] += a0 * bv.y; acc[0][2] += a0 * bv.z; acc[0][3] += a0 * bv.w;
        acc[1][0] += a1 * bv.x; acc[1][1] += a1 * bv.y; acc[1][2] += a1 * bv.z; acc[1][3] += a1 * bv.w;
        acc[2][0] += a2 * bv.x; acc[2][1] += a2 * bv.y; acc[2][2] += a2 * bv.z; acc[2][3] += a2 * bv.w;
        acc[3][0] += a3 * bv.x; acc[3][1] += a3 * bv.y; acc[3][2] += a3 * bv.z; acc[3][3] += a3 * bv.w;
    }
    __syncthreads();   // done reading ksT

    // ---- mask + stage P into ksT's space ----
    float* ps = ksT;
#pragma unroll
    for (int di = 0; di < 4; ++di) {
        int ii = i0 + di;
        float4 w;
        w.x = (j0 + 0 <= ii) ? acc[di][0] : 0.0f;
        w.y = (j0 + 1 <= ii) ? acc[di][1] : 0.0f;
        w.z = (j0 + 2 <= ii) ? acc[di][2] : 0.0f;
        w.w = (j0 + 3 <= ii) ? acc[di][3] : 0.0f;
        *(float4*)&ps[ii * NCK + j0] = w;
    }
    __syncthreads();

    // ---- GEMM2a: O = P.V ----
    float o[4][4];
#pragma unroll
    for (int di = 0; di < 4; ++di)
#pragma unroll
        for (int ei = 0; ei < 4; ++ei) o[di][ei] = 0.0f;

#pragma unroll 8
    for (int j = 0; j < NCK; ++j) {
        float a0 = ps[(i0 + 0) * NCK + j];
        float a1 = ps[(i0 + 1) * NCK + j];
        float a2 = ps[(i0 + 2) * NCK + j];
        float a3 = ps[(i0 + 3) * NCK + j];
        float4 bv = *(const float4*)(vs + j * PST + j0);
        o[0][0] += a0 * bv.x; o[0][1] += a0 * bv.y; o[0][2] += a0 * bv.z; o[0][3] += a0 * bv.w;
        o[1][0] += a1 * bv.x; o[1][1] += a1 * bv.y; o[1][2] += a1 * bv.z; o[1][3] += a1 * bv.w;
        o[2][0] += a2 * bv.x; o[2][1] += a2 * bv.y; o[2][2] += a2 * bv.z; o[2][3] += a2 * bv.w;
        o[3][0] += a3 * bv.x; o[3][1] += a3 * bv.y; o[3][2] += a3 * bv.z; o[3][3] += a3 * bv.w;
    }
    __syncthreads();   // done reading vs

    // ---- stage St over vs ----
    {
        const float* stg = g_St + ((size_t)bh * NNC + c) * ND * ND;
#pragma unroll
        for (int t = 0; t < 16; ++t) {
            int idx = tid + t * 256;
            int r = idx >> 6, e = idx & 63;
            vs[r * PST + e] = stg[idx];
        }
    }
    __syncthreads();

    // ---- GEMM2b: O += Q'.St ----
    float* sts = vs;
#pragma unroll 8
    for (int d = 0; d < ND; ++d) {
        float a0 = qs[(i0 + 0) * PST + d];
        float a1 = qs[(i0 + 1) * PST + d];
        float a2 = qs[(i0 + 2) * PST + d];
        float a3 = qs[(i0 + 3) * PST + d];
        float4 bv = *(const float4*)(sts + d * PST + j0);
        o[0][0] += a0 * bv.x; o[0][1] += a0 * bv.y; o[0][2] += a0 * bv.z; o[0][3] += a0 * bv.w;
        o[1][0] += a1 * bv.x; o[1][1] += a1 * bv.y; o[1][2] += a1 * bv.z; o[1][3] += a1 * bv.w;
        o[2][0] += a2 * bv.x; o[2][1] += a2 * bv.y; o[2][2] += a2 * bv.z; o[2][3] += a2 * bv.w;
        o[3][0] += a3 * bv.x; o[3][1] += a3 * bv.y; o[3][2] += a3 * bv.z; o[3][3] += a3 * bv.w;
    }

    float* og = out + ((size_t)(b * NS + c0)) * NHID + h * ND;
#pragma unroll
    for (int di = 0; di < 4; ++di) {
        float4 w = make_float4(o[di][0], o[di][1], o[di][2], o[di][3]);
        *(float4*)&og[(size_t)(i0 + di) * NHID + j0] = w;
    }
}

// ---------------------------------------------------------------------------
extern "C" void kernel_launch(void* const* d_in, const int* in_sizes, int n_in,
                              void* d_out, int out_size) {
    (void)in_sizes; (void)n_in; (void)out_size;
    const float* Q = (const float*)d_in[0];
    const float* K = (const float*)d_in[1];
    const float* V = (const float*)d_in[2];
    float* out = (float*)d_out;

    table_kernel<<<(NS * 32) / 256, 256>>>();
    rope_lite_kernel<<<(NBH * NS * 16) / 256, 256>>>(Q, K);

    dim3 grid(NNC, NH, NB);
    passA_kernel<<<grid, 256>>>(V);
    scan_kernel<<<(NBH * 4096) / 256, 256>>>();

    size_t shm = (size_t)(2 * NCK * PST + NCK * NCK + 2 * NCK) * sizeof(float);  // 51712 B
    cudaFuncSetAttribute(passC_kernel, cudaFuncAttributeMaxDynamicSharedMemorySize, (int)shm);
    passC_kernel<<<grid, 256, shm>>>(V, out);
}

// round 13
// speedup vs baseline: 1.5892x; 1.1435x over previous
#include <cuda_runtime.h>
#include <math.h>

// Problem constants
#define NB   2
#define NS   2048
#define NH   16
#define ND   64
#define NHID 1024
#define NCK  64      // chunk size
#define NNC  32      // chunks per sequence
#define NBH  32      // NB*NH
#define PST  68      // padded smem row stride (floats)

typedef unsigned long long u64;

// Scratch (static device globals -- no allocation allowed)
__device__ float4 g_tab[NS * 32];              // xPos table: (cos*sc, sin*sc, cos/sc, sin/sc)
__device__ float  g_qr[NBH * NS * ND];         // rotated Q, [bh][s][d]
__device__ float  g_kr[NBH * NS * ND];         // rotated K, [bh][s][d]
__device__ float  g_A [NBH * NNC * ND * ND];   // per-chunk state contributions
__device__ float  g_St[NBH * NNC * ND * ND];   // prefix-scanned states (state BEFORE chunk c)

__device__ __forceinline__ double head_lg(int h) {
    const double L0 = -3.4657359027997265;   // log(1/32)
    const double L1 = -6.2383246250395075;   // log(1/512)
    double g = 1.0 - exp(L0 + (L1 - L0) * ((double)h / 15.0));
    return log(g);
}

// ---- packed f32x2 helpers ----
__device__ __forceinline__ u64 pk2(float x) {
    unsigned xi = __float_as_uint(x);
    u64 r; asm("mov.b64 %0, {%1, %1};" : "=l"(r) : "r"(xi)); return r;
}
__device__ __forceinline__ u64 ffma2(u64 a, u64 b, u64 c) {
    u64 d; asm("fma.rn.f32x2 %0, %1, %2, %3;" : "=l"(d) : "l"(a), "l"(b), "l"(c)); return d;
}
__device__ __forceinline__ float2 up2(u64 v) {
    unsigned lo, hi; asm("mov.b64 {%0, %1}, %2;" : "=r"(lo), "=r"(hi) : "l"(v));
    return make_float2(__uint_as_float(lo), __uint_as_float(hi));
}

// ---------------------------------------------------------------------------
// Kernel 0: xPos table. tab[s][i] = (cos*sc, sin*sc, cos/sc, sin/sc)
// ---------------------------------------------------------------------------
__global__ __launch_bounds__(256)
void table_kernel() {
    int idx = blockIdx.x * 256 + threadIdx.x;   // [0, 2048*32)
    int i = idx & 31;
    int s = idx >> 5;
    float invf = (float)(1.0 / pow(10000.0, (double)i / 32.0));
    float bs   = (2.0f * (float)i + 25.6f) / 89.6f;   // (2i + 0.4*64)/(1.4*64)
    float pos  = (float)s;
    float sn, cs;
    sincosf(pos * invf, &sn, &cs);
    float sc = powf(bs, pos * (1.0f / 512.0f));
    float iv = 1.0f / sc;
    g_tab[idx] = make_float4(cs * sc, sn * sc, cs * iv, sn * iv);
}

// ---------------------------------------------------------------------------
// Kernel 0.5: rope_lite v2 -- 4 floats per thread (float4 in/out), table-based.
// ---------------------------------------------------------------------------
__global__ __launch_bounds__(256)
void rope_lite_kernel(const float* __restrict__ Q, const float* __restrict__ K) {
    int idx = blockIdx.x * 256 + threadIdx.x;  // [0, NBH*NS*16)
    int iq = idx & 15;                          // quad index, d0 = 4*iq
    int s  = (idx >> 4) & (NS - 1);
    int bh = idx >> 15;
    int h  = bh & (NH - 1);
    int b  = bh >> 4;
    int d0 = 4 * iq;

    float4 t0 = g_tab[(s << 5) + 2 * iq];      // pairs 2iq, 2iq+1
    float4 t1 = g_tab[(s << 5) + 2 * iq + 1];

    int gin = (b * NS + s) * NHID + h * ND + d0;
    float4 q = *(const float4*)(Q + gin);
    float4 k = *(const float4*)(K + gin);

    float4 qo, ko;
    qo.x = q.x * t0.x - q.y * t0.y;
    qo.y = q.y * t0.x + q.x * t0.y;
    qo.z = q.z * t1.x - q.w * t1.y;
    qo.w = q.w * t1.x + q.z * t1.y;
    ko.x = k.x * t0.z - k.y * t0.w;
    ko.y = k.y * t0.z + k.x * t0.w;
    ko.z = k.z * t1.z - k.w * t1.w;
    ko.w = k.w * t1.z + k.z * t1.w;

    int gout = (bh * NS + s) * ND + d0;
    *(float4*)(g_qr + gout) = qo;
    *(float4*)(g_kr + gout) = ko;
}

// ---------------------------------------------------------------------------
// Kernel 1: A_c[d][e] = sum_j gamma^(C-j) k'[j][d] v[j][e]   (Round-10 proven)
// ---------------------------------------------------------------------------
__global__ __launch_bounds__(256)
void passA_kernel(const float* __restrict__ V) {
    __shared__ float ks[NCK * PST];
    __shared__ float vs[NCK * PST];
    __shared__ float wr[NCK];

    int c = blockIdx.x, h = blockIdx.y, b = blockIdx.z;
    int bh = b * NH + h;
    int tid = threadIdx.x;

    if (tid < NCK) {
        double lg = head_lg(h);
        wr[tid] = (float)exp(lg * (double)(NCK - tid));   // gamma^(C-j)
    }
    __syncthreads();

    int c0 = c * NCK;
    const float* kg = g_kr + (bh * NS + c0) * ND;
    const float* vg = V + (b * NS + c0) * NHID + h * ND;

#pragma unroll
    for (int t = 0; t < 16; ++t) {
        int idx = tid + t * 256;
        int r = idx >> 6, d = idx & 63;
        ks[r * PST + d] = kg[r * ND + d] * wr[r];
        vs[r * PST + d] = vg[r * NHID + d];
    }
    __syncthreads();

    int ty = tid >> 4, tx = tid & 15;
    float acc[4][4];
#pragma unroll
    for (int di = 0; di < 4; ++di)
#pragma unroll
        for (int ei = 0; ei < 4; ++ei) acc[di][ei] = 0.0f;

#pragma unroll 8
    for (int j = 0; j < NCK; ++j) {
        float a0 = ks[j * PST + 4 * ty + 0];
        float a1 = ks[j * PST + 4 * ty + 1];
        float a2 = ks[j * PST + 4 * ty + 2];
        float a3 = ks[j * PST + 4 * ty + 3];
        float4 bv = *(const float4*)(vs + j * PST + 4 * tx);
        acc[0][0] += a0 * bv.x; acc[0][1] += a0 * bv.y; acc[0][2] += a0 * bv.z; acc[0][3] += a0 * bv.w;
        acc[1][0] += a1 * bv.x; acc[1][1] += a1 * bv.y; acc[1][2] += a1 * bv.z; acc[1][3] += a1 * bv.w;
        acc[2][0] += a2 * bv.x; acc[2][1] += a2 * bv.y; acc[2][2] += a2 * bv.z; acc[2][3] += a2 * bv.w;
        acc[3][0] += a3 * bv.x; acc[3][1] += a3 * bv.y; acc[3][2] += a3 * bv.z; acc[3][3] += a3 * bv.w;
    }

    float* ag = g_A + ((size_t)bh * NNC + c) * ND * ND;
#pragma unroll
    for (int di = 0; di < 4; ++di) {
        float4 w = make_float4(acc[di][0], acc[di][1], acc[di][2], acc[di][3]);
        *(float4*)&ag[(4 * ty + di) * ND + 4 * tx] = w;
    }
}

// ---------------------------------------------------------------------------
// Kernel 2: prefix scan (Round-10 PROVEN: 128 CTAs, float4, depth-8 pipeline).
// ---------------------------------------------------------------------------
__global__ __launch_bounds__(256)
void scan_kernel() {
    int blk = blockIdx.x;          // NBH*4
    int bh = blk >> 2;
    int qtr = blk & 3;
    int h = bh & (NH - 1);
    int tid = threadIdx.x;
    double lg = head_lg(h);
    float dec = (float)exp(lg * (double)NCK);

    size_t base = (size_t)bh * NNC * ND * ND + qtr * 1024 + tid * 4;

    float4 buf[8];
#pragma unroll
    for (int p = 0; p < 8; ++p)
        buf[p] = *(const float4*)(g_A + base + (size_t)p * ND * ND);

    float4 st = make_float4(0.f, 0.f, 0.f, 0.f);
#pragma unroll
    for (int c = 0; c < NNC; ++c) {
        *(float4*)(g_St + base + (size_t)c * ND * ND) = st;
        float4 a = buf[c & 7];
        if (c + 8 < NNC)
            buf[c & 7] = *(const float4*)(g_A + base + (size_t)(c + 8) * ND * ND);
        st.x = st.x * dec + a.x;
        st.y = st.y * dec + a.y;
        st.z = st.z * dec + a.z;
        st.w = st.w * dec + a.w;
    }
}

// ---------------------------------------------------------------------------
// Kernel 3: per-chunk output. Round-10 structure (256 thr, 4 CTAs/SM, smem
// reuse), GEMM bodies converted to packed f32x2 (8 FFMA2 vs 16 FFMA per iter).
// ---------------------------------------------------------------------------
extern __shared__ float smC[];

__global__ __launch_bounds__(256, 4)
void passC_kernel(const float* __restrict__ V, float* __restrict__ out) {
    float* qs  = smC;                            // [i][d]  NCK*PST
    float* ksT = smC + NCK * PST;                // [d][j] swizzled; reused as ps[i][j]
    float* vs  = smC + NCK * PST + NCK * NCK;    // [j][e]; reused as sts[d'][e]
    float* wq  = vs + NCK * PST;                 // [NCK] gamma^i
    float* wk  = wq + NCK;                       // [NCK] gamma^{-j}

    int c = blockIdx.x, h = blockIdx.y, b = blockIdx.z;
    int bh = b * NH + h;
    int tid = threadIdx.x;
    int c0 = c * NCK;

    if (tid < NCK) {
        double lg = head_lg(h);
        wq[tid] = (float)exp(lg * (double)tid);
        wk[tid] = (float)exp(-lg * (double)tid);
    }
    __syncthreads();

    const float* qg = g_qr + (bh * NS + c0) * ND;
    const float* kg = g_kr + (bh * NS + c0) * ND;
    const float* vg = V + (b * NS + c0) * NHID + h * ND;

#pragma unroll
    for (int t = 0; t < 16; ++t) {
        int idx = tid + t * 256;
        int r = idx >> 6, d = idx & 63;
        qs[r * PST + d] = qg[r * ND + d] * wq[r];
        float kv = kg[r * ND + d] * wk[r];
        ksT[d * NCK + (((r >> 2) ^ (d & 15)) << 2) + (r & 3)] = kv;
        vs[r * PST + d] = vg[r * NHID + d];
    }
    __syncthreads();

    int ty = tid >> 4, tx = tid & 15;
    int i0 = 4 * ty, j0 = 4 * tx;

    // ---- GEMM1: P = Q'.K'^T (f32x2) ----
    u64 acc[4][2];
#pragma unroll
    for (int r = 0; r < 4; ++r) { acc[r][0] = 0ull; acc[r][1] = 0ull; }

#pragma unroll 8
    for (int d = 0; d < ND; ++d) {
        u64 a0 = pk2(qs[(i0 + 0) * PST + d]);
        u64 a1 = pk2(qs[(i0 + 1) * PST + d]);
        u64 a2 = pk2(qs[(i0 + 2) * PST + d]);
        u64 a3 = pk2(qs[(i0 + 3) * PST + d]);
        ulonglong2 kb = *(const ulonglong2*)&ksT[d * NCK + ((tx ^ (d & 15)) << 2)];
        acc[0][0] = ffma2(a0, kb.x, acc[0][0]); acc[0][1] = ffma2(a0, kb.y, acc[0][1]);
        acc[1][0] = ffma2(a1, kb.x, acc[1][0]); acc[1][1] = ffma2(a1, kb.y, acc[1][1]);
        acc[2][0] = ffma2(a2, kb.x, acc[2][0]); acc[2][1] = ffma2(a2, kb.y, acc[2][1]);
        acc[3][0] = ffma2(a3, kb.x, acc[3][0]); acc[3][1] = ffma2(a3, kb.y, acc[3][1]);
    }
    __syncthreads();   // done reading ksT

    // ---- mask + stage P into ksT's space ----
    float* ps = ksT;
#pragma unroll
    for (int di = 0; di < 4; ++di) {
        int ii = i0 + di;
        float2 vA = up2(acc[di][0]);
        float2 vB = up2(acc[di][1]);
        float4 w;
        w.x = (j0 + 0 <= ii) ? vA.x : 0.0f;
        w.y = (j0 + 1 <= ii) ? vA.y : 0.0f;
        w.z = (j0 + 2 <= ii) ? vB.x : 0.0f;
        w.w = (j0 + 3 <= ii) ? vB.y : 0.0f;
        *(float4*)&ps[ii * NCK + j0] = w;
    }
    __syncthreads();

    // ---- GEMM2a: O = P.V (f32x2) ----
    u64 o[4][2];
#pragma unroll
    for (int r = 0; r < 4; ++r) { o[r][0] = 0ull; o[r][1] = 0ull; }

#pragma unroll 8
    for (int j = 0; j < NCK; ++j) {
        u64 a0 = pk2(ps[(i0 + 0) * NCK + j]);
        u64 a1 = pk2(ps[(i0 + 1) * NCK + j]);
        u64 a2 = pk2(ps[(i0 + 2) * NCK + j]);
        u64 a3 = pk2(ps[(i0 + 3) * NCK + j]);
        ulonglong2 bb = *(const ulonglong2*)(vs + j * PST + j0);
        o[0][0] = ffma2(a0, bb.x, o[0][0]); o[0][1] = ffma2(a0, bb.y, o[0][1]);
        o[1][0] = ffma2(a1, bb.x, o[1][0]); o[1][1] = ffma2(a1, bb.y, o[1][1]);
        o[2][0] = ffma2(a2, bb.x, o[2][0]); o[2][1] = ffma2(a2, bb.y, o[2][1]);
        o[3][0] = ffma2(a3, bb.x, o[3][0]); o[3][1] = ffma2(a3, bb.y, o[3][1]);
    }
    __syncthreads();   // done reading vs

    // ---- stage St over vs ----
    {
        const float* stg = g_St + ((size_t)bh * NNC + c) * ND * ND;
#pragma unroll
        for (int t = 0; t < 16; ++t) {
            int idx = tid + t * 256;
            int r = idx >> 6, e = idx & 63;
            vs[r * PST + e] = stg[idx];
        }
    }
    __syncthreads();

    // ---- GEMM2b: O += Q'.St (f32x2) ----
    float* sts = vs;
#pragma unroll 8
    for (int d = 0; d < ND; ++d) {
        u64 a0 = pk2(qs[(i0 + 0) * PST + d]);
        u64 a1 = pk2(qs[(i0 + 1) * PST + d]);
        u64 a2 = pk2(qs[(i0 + 2) * PST + d]);
        u64 a3 = pk2(qs[(i0 + 3) * PST + d]);
        ulonglong2 bb = *(const ulonglong2*)(sts + d * PST + j0);
        o[0][0] = ffma2(a0, bb.x, o[0][0]); o[0][1] = ffma2(a0, bb.y, o[0][1]);
        o[1][0] = ffma2(a1, bb.x, o[1][0]); o[1][1] = ffma2(a1, bb.y, o[1][1]);
        o[2][0] = ffma2(a2, bb.x, o[2][0]); o[2][1] = ffma2(a2, bb.y, o[2][1]);
        o[3][0] = ffma2(a3, bb.x, o[3][0]); o[3][1] = ffma2(a3, bb.y, o[3][1]);
    }

    float* og = out + ((size_t)(b * NS + c0)) * NHID + h * ND;
#pragma unroll
    for (int di = 0; di < 4; ++di) {
        float2 pA = up2(o[di][0]);
        float2 pB = up2(o[di][1]);
        *(float4*)&og[(size_t)(i0 + di) * NHID + j0] = make_float4(pA.x, pA.y, pB.x, pB.y);
    }
}

// ---------------------------------------------------------------------------
extern "C" void kernel_launch(void* const* d_in, const int* in_sizes, int n_in,
                              void* d_out, int out_size) {
    (void)in_sizes; (void)n_in; (void)out_size;
    const float* Q = (const float*)d_in[0];
    const float* K = (const float*)d_in[1];
    const float* V = (const float*)d_in[2];
    float* out = (float*)d_out;

    table_kernel<<<(NS * 32) / 256, 256>>>();
    rope_lite_kernel<<<(NBH * NS * 16) / 256, 256>>>(Q, K);

    dim3 grid(NNC, NH, NB);
    passA_kernel<<<grid, 256>>>(V);
    scan_kernel<<<NBH * 4, 256>>>();

    size_t shm = (size_t)(2 * NCK * PST + NCK * NCK + 2 * NCK) * sizeof(float);  // 51712 B
    cudaFuncSetAttribute(passC_kernel, cudaFuncAttributeMaxDynamicSharedMemorySize, (int)shm);
    passC_kernel<<<grid, 256, shm>>>(V, out);
}

// round 14
// speedup vs baseline: 1.5996x; 1.0065x over previous
#include <cuda_runtime.h>
#include <math.h>

// Problem constants
#define NB   2
#define NS   2048
#define NH   16
#define ND   64
#define NHID 1024
#define NCK  64      // chunk size
#define NNC  32      // chunks per sequence
#define NBH  32      // NB*NH
#define PST  68      // padded smem row stride (floats)

typedef unsigned long long u64;

// Scratch (static device globals -- no allocation allowed)
__device__ float4 g_tab[NS * 32];              // xPos table: (cos*sc, sin*sc, cos/sc, sin/sc)
__device__ float  g_qr[NBH * NS * ND];         // rotated Q, [bh][s][d]
__device__ float  g_kr[NBH * NS * ND];         // rotated K, [bh][s][d]
__device__ float  g_A [NBH * NNC * ND * ND];   // per-chunk state contributions
__device__ float  g_St[NBH * NNC * ND * ND];   // prefix-scanned states (state BEFORE chunk c)

__device__ __forceinline__ double head_lg(int h) {
    const double L0 = -3.4657359027997265;   // log(1/32)
    const double L1 = -6.2383246250395075;   // log(1/512)
    double g = 1.0 - exp(L0 + (L1 - L0) * ((double)h / 15.0));
    return log(g);
}

// ---- packed f32x2 helpers ----
__device__ __forceinline__ u64 pk2(float x) {
    unsigned xi = __float_as_uint(x);
    u64 r; asm("mov.b64 %0, {%1, %1};" : "=l"(r) : "r"(xi)); return r;
}
__device__ __forceinline__ u64 ffma2(u64 a, u64 b, u64 c) {
    u64 d; asm("fma.rn.f32x2 %0, %1, %2, %3;" : "=l"(d) : "l"(a), "l"(b), "l"(c)); return d;
}
__device__ __forceinline__ float2 up2(u64 v) {
    unsigned lo, hi; asm("mov.b64 {%0, %1}, %2;" : "=r"(lo), "=r"(hi) : "l"(v));
    return make_float2(__uint_as_float(lo), __uint_as_float(hi));
}

// ---------------------------------------------------------------------------
// Kernel 0: xPos table. tab[s][i] = (cos*sc, sin*sc, cos/sc, sin/sc)
// ---------------------------------------------------------------------------
__global__ __launch_bounds__(256)
void table_kernel() {
    int idx = blockIdx.x * 256 + threadIdx.x;   // [0, 2048*32)
    int i = idx & 31;
    int s = idx >> 5;
    float invf = (float)(1.0 / pow(10000.0, (double)i / 32.0));
    float bs   = (2.0f * (float)i + 25.6f) / 89.6f;   // (2i + 0.4*64)/(1.4*64)
    float pos  = (float)s;
    float sn, cs;
    sincosf(pos * invf, &sn, &cs);
    float sc = powf(bs, pos * (1.0f / 512.0f));
    float iv = 1.0f / sc;
    g_tab[idx] = make_float4(cs * sc, sn * sc, cs * iv, sn * iv);
}

// ---------------------------------------------------------------------------
// Kernel 0.5: rope_lite v2 -- 4 floats per thread (float4 in/out), table-based.
// ---------------------------------------------------------------------------
__global__ __launch_bounds__(256)
void rope_lite_kernel(const float* __restrict__ Q, const float* __restrict__ K) {
    int idx = blockIdx.x * 256 + threadIdx.x;  // [0, NBH*NS*16)
    int iq = idx & 15;                          // quad index, d0 = 4*iq
    int s  = (idx >> 4) & (NS - 1);
    int bh = idx >> 15;
    int h  = bh & (NH - 1);
    int b  = bh >> 4;
    int d0 = 4 * iq;

    float4 t0 = g_tab[(s << 5) + 2 * iq];      // pairs 2iq, 2iq+1
    float4 t1 = g_tab[(s << 5) + 2 * iq + 1];

    int gin = (b * NS + s) * NHID + h * ND + d0;
    float4 q = *(const float4*)(Q + gin);
    float4 k = *(const float4*)(K + gin);

    float4 qo, ko;
    qo.x = q.x * t0.x - q.y * t0.y;
    qo.y = q.y * t0.x + q.x * t0.y;
    qo.z = q.z * t1.x - q.w * t1.y;
    qo.w = q.w * t1.x + q.z * t1.y;
    ko.x = k.x * t0.z - k.y * t0.w;
    ko.y = k.y * t0.z + k.x * t0.w;
    ko.z = k.z * t1.z - k.w * t1.w;
    ko.w = k.w * t1.z + k.z * t1.w;

    int gout = (bh * NS + s) * ND + d0;
    *(float4*)(g_qr + gout) = qo;
    *(float4*)(g_kr + gout) = ko;
}

// ---------------------------------------------------------------------------
// Kernel 1: A_c[d][e] = sum_j gamma^(C-j) k'[j][d] v[j][e]
// GEMM body converted to f32x2 (mirror of the proven passC change).
// ---------------------------------------------------------------------------
__global__ __launch_bounds__(256)
void passA_kernel(const float* __restrict__ V) {
    __shared__ float ks[NCK * PST];
    __shared__ float vs[NCK * PST];
    __shared__ float wr[NCK];

    int c = blockIdx.x, h = blockIdx.y, b = blockIdx.z;
    int bh = b * NH + h;
    int tid = threadIdx.x;

    if (tid < NCK) {
        double lg = head_lg(h);
        wr[tid] = (float)exp(lg * (double)(NCK - tid));   // gamma^(C-j)
    }
    __syncthreads();

    int c0 = c * NCK;
    const float* kg = g_kr + (bh * NS + c0) * ND;
    const float* vg = V + (b * NS + c0) * NHID + h * ND;

#pragma unroll
    for (int t = 0; t < 16; ++t) {
        int idx = tid + t * 256;
        int r = idx >> 6, d = idx & 63;
        ks[r * PST + d] = kg[r * ND + d] * wr[r];
        vs[r * PST + d] = vg[r * NHID + d];
    }
    __syncthreads();

    int ty = tid >> 4, tx = tid & 15;
    u64 acc[4][2];
#pragma unroll
    for (int r = 0; r < 4; ++r) { acc[r][0] = 0ull; acc[r][1] = 0ull; }

#pragma unroll 8
    for (int j = 0; j < NCK; ++j) {
        u64 a0 = pk2(ks[j * PST + 4 * ty + 0]);
        u64 a1 = pk2(ks[j * PST + 4 * ty + 1]);
        u64 a2 = pk2(ks[j * PST + 4 * ty + 2]);
        u64 a3 = pk2(ks[j * PST + 4 * ty + 3]);
        ulonglong2 bb = *(const ulonglong2*)(vs + j * PST + 4 * tx);
        acc[0][0] = ffma2(a0, bb.x, acc[0][0]); acc[0][1] = ffma2(a0, bb.y, acc[0][1]);
        acc[1][0] = ffma2(a1, bb.x, acc[1][0]); acc[1][1] = ffma2(a1, bb.y, acc[1][1]);
        acc[2][0] = ffma2(a2, bb.x, acc[2][0]); acc[2][1] = ffma2(a2, bb.y, acc[2][1]);
        acc[3][0] = ffma2(a3, bb.x, acc[3][0]); acc[3][1] = ffma2(a3, bb.y, acc[3][1]);
    }

    float* ag = g_A + ((size_t)bh * NNC + c) * ND * ND;
#pragma unroll
    for (int di = 0; di < 4; ++di) {
        float2 pA = up2(acc[di][0]);
        float2 pB = up2(acc[di][1]);
        *(float4*)&ag[(4 * ty + di) * ND + 4 * tx] = make_float4(pA.x, pA.y, pB.x, pB.y);
    }
}

// ---------------------------------------------------------------------------
// Kernel 2: prefix scan -- proven structure, pipeline deepened 8 -> 16 to
// cover the full L2 round trip (~234 cyc) with in-flight loads.
// ---------------------------------------------------------------------------
__global__ __launch_bounds__(256)
void scan_kernel() {
    int blk = blockIdx.x;          // NBH*4
    int bh = blk >> 2;
    int qtr = blk & 3;
    int h = bh & (NH - 1);
    int tid = threadIdx.x;
    double lg = head_lg(h);
    float dec = (float)exp(lg * (double)NCK);

    size_t base = (size_t)bh * NNC * ND * ND + qtr * 1024 + tid * 4;

    float4 buf[16];
#pragma unroll
    for (int p = 0; p < 16; ++p)
        buf[p] = *(const float4*)(g_A + base + (size_t)p * ND * ND);

    float4 st = make_float4(0.f, 0.f, 0.f, 0.f);
#pragma unroll
    for (int c = 0; c < NNC; ++c) {
        *(float4*)(g_St + base + (size_t)c * ND * ND) = st;
        float4 a = buf[c & 15];
        if (c + 16 < NNC)
            buf[c & 15] = *(const float4*)(g_A + base + (size_t)(c + 16) * ND * ND);
        st.x = st.x * dec + a.x;
        st.y = st.y * dec + a.y;
        st.z = st.z * dec + a.z;
        st.w = st.w * dec + a.w;
    }
}

// ---------------------------------------------------------------------------
// Kernel 3: per-chunk output (Round-13 proven: 256 thr, 4 CTAs/SM, f32x2).
// ---------------------------------------------------------------------------
extern __shared__ float smC[];

__global__ __launch_bounds__(256, 4)
void passC_kernel(const float* __restrict__ V, float* __restrict__ out) {
    float* qs  = smC;                            // [i][d]  NCK*PST
    float* ksT = smC + NCK * PST;                // [d][j] swizzled; reused as ps[i][j]
    float* vs  = smC + NCK * PST + NCK * NCK;    // [j][e]; reused as sts[d'][e]
    float* wq  = vs + NCK * PST;                 // [NCK] gamma^i
    float* wk  = wq + NCK;                       // [NCK] gamma^{-j}

    int c = blockIdx.x, h = blockIdx.y, b = blockIdx.z;
    int bh = b * NH + h;
    int tid = threadIdx.x;
    int c0 = c * NCK;

    if (tid < NCK) {
        double lg = head_lg(h);
        wq[tid] = (float)exp(lg * (double)tid);
        wk[tid] = (float)exp(-lg * (double)tid);
    }
    __syncthreads();

    const float* qg = g_qr + (bh * NS + c0) * ND;
    const float* kg = g_kr + (bh * NS + c0) * ND;
    const float* vg = V + (b * NS + c0) * NHID + h * ND;

#pragma unroll
    for (int t = 0; t < 16; ++t) {
        int idx = tid + t * 256;
        int r = idx >> 6, d = idx & 63;
        qs[r * PST + d] = qg[r * ND + d] * wq[r];
        float kv = kg[r * ND + d] * wk[r];
        ksT[d * NCK + (((r >> 2) ^ (d & 15)) << 2) + (r & 3)] = kv;
        vs[r * PST + d] = vg[r * NHID + d];
    }
    __syncthreads();

    int ty = tid >> 4, tx = tid & 15;
    int i0 = 4 * ty, j0 = 4 * tx;

    // ---- GEMM1: P = Q'.K'^T (f32x2) ----
    u64 acc[4][2];
#pragma unroll
    for (int r = 0; r < 4; ++r) { acc[r][0] = 0ull; acc[r][1] = 0ull; }

#pragma unroll 8
    for (int d = 0; d < ND; ++d) {
        u64 a0 = pk2(qs[(i0 + 0) * PST + d]);
        u64 a1 = pk2(qs[(i0 + 1) * PST + d]);
        u64 a2 = pk2(qs[(i0 + 2) * PST + d]);
        u64 a3 = pk2(qs[(i0 + 3) * PST + d]);
        ulonglong2 kb = *(const ulonglong2*)&ksT[d * NCK + ((tx ^ (d & 15)) << 2)];
        acc[0][0] = ffma2(a0, kb.x, acc[0][0]); acc[0][1] = ffma2(a0, kb.y, acc[0][1]);
        acc[1][0] = ffma2(a1, kb.x, acc[1][0]); acc[1][1] = ffma2(a1, kb.y, acc[1][1]);
        acc[2][0] = ffma2(a2, kb.x, acc[2][0]); acc[2][1] = ffma2(a2, kb.y, acc[2][1]);
        acc[3][0] = ffma2(a3, kb.x, acc[3][0]); acc[3][1] = ffma2(a3, kb.y, acc[3][1]);
    }
    __syncthreads();   // done reading ksT

    // ---- mask + stage P into ksT's space ----
    float* ps = ksT;
#pragma unroll
    for (int di = 0; di < 4; ++di) {
        int ii = i0 + di;
        float2 vA = up2(acc[di][0]);
        float2 vB = up2(acc[di][1]);
        float4 w;
        w.x = (j0 + 0 <= ii) ? vA.x : 0.0f;
        w.y = (j0 + 1 <= ii) ? vA.y : 0.0f;
        w.z = (j0 + 2 <= ii) ? vB.x : 0.0f;
        w.w = (j0 + 3 <= ii) ? vB.y : 0.0f;
        *(float4*)&ps[ii * NCK + j0] = w;
    }
    __syncthreads();

    // ---- GEMM2a: O = P.V (f32x2) ----
    u64 o[4][2];
#pragma unroll
    for (int r = 0; r < 4; ++r) { o[r][0] = 0ull; o[r][1] = 0ull; }

#pragma unroll 8
    for (int j = 0; j < NCK; ++j) {
        u64 a0 = pk2(ps[(i0 + 0) * NCK + j]);
        u64 a1 = pk2(ps[(i0 + 1) * NCK + j]);
        u64 a2 = pk2(ps[(i0 + 2) * NCK + j]);
        u64 a3 = pk2(ps[(i0 + 3) * NCK + j]);
        ulonglong2 bb = *(const ulonglong2*)(vs + j * PST + j0);
        o[0][0] = ffma2(a0, bb.x, o[0][0]); o[0][1] = ffma2(a0, bb.y, o[0][1]);
        o[1][0] = ffma2(a1, bb.x, o[1][0]); o[1][1] = ffma2(a1, bb.y, o[1][1]);
        o[2][0] = ffma2(a2, bb.x, o[2][0]); o[2][1] = ffma2(a2, bb.y, o[2][1]);
        o[3][0] = ffma2(a3, bb.x, o[3][0]); o[3][1] = ffma2(a3, bb.y, o[3][1]);
    }
    __syncthreads();   // done reading vs

    // ---- stage St over vs ----
    {
        const float* stg = g_St + ((size_t)bh * NNC + c) * ND * ND;
#pragma unroll
        for (int t = 0; t < 16; ++t) {
            int idx = tid + t * 256;
            int r = idx >> 6, e = idx & 63;
            vs[r * PST + e] = stg[idx];
        }
    }
    __syncthreads();

    // ---- GEMM2b: O += Q'.St (f32x2) ----
    float* sts = vs;
#pragma unroll 8
    for (int d = 0; d < ND; ++d) {
        u64 a0 = pk2(qs[(i0 + 0) * PST + d]);
        u64 a1 = pk2(qs[(i0 + 1) * PST + d]);
        u64 a2 = pk2(qs[(i0 + 2) * PST + d]);
        u64 a3 = pk2(qs[(i0 + 3) * PST + d]);
        ulonglong2 bb = *(const ulonglong2*)(sts + d * PST + j0);
        o[0][0] = ffma2(a0, bb.x, o[0][0]); o[0][1] = ffma2(a0, bb.y, o[0][1]);
        o[1][0] = ffma2(a1, bb.x, o[1][0]); o[1][1] = ffma2(a1, bb.y, o[1][1]);
        o[2][0] = ffma2(a2, bb.x, o[2][0]); o[2][1] = ffma2(a2, bb.y, o[2][1]);
        o[3][0] = ffma2(a3, bb.x, o[3][0]); o[3][1] = ffma2(a3, bb.y, o[3][1]);
    }

    float* og = out + ((size_t)(b * NS + c0)) * NHID + h * ND;
#pragma unroll
    for (int di = 0; di < 4; ++di) {
        float2 pA = up2(o[di][0]);
        float2 pB = up2(o[di][1]);
        *(float4*)&og[(size_t)(i0 + di) * NHID + j0] = make_float4(pA.x, pA.y, pB.x, pB.y);
    }
}

// ---------------------------------------------------------------------------
extern "C" void kernel_launch(void* const* d_in, const int* in_sizes, int n_in,
                              void* d_out, int out_size) {
    (void)in_sizes; (void)n_in; (void)out_size;
    const float* Q = (const float*)d_in[0];
    const float* K = (const float*)d_in[1];
    const float* V = (const float*)d_in[2];
    float* out = (float*)d_out;

    table_kernel<<<(NS * 32) / 256, 256>>>();
    rope_lite_kernel<<<(NBH * NS * 16) / 256, 256>>>(Q, K);

    dim3 grid(NNC, NH, NB);
    passA_kernel<<<grid, 256>>>(V);
    scan_kernel<<<NBH * 4, 256>>>();

    size_t shm = (size_t)(2 * NCK * PST + NCK * NCK + 2 * NCK) * sizeof(float);  // 51712 B
    cudaFuncSetAttribute(passC_kernel, cudaFuncAttributeMaxDynamicSharedMemorySize, (int)shm);
    passC_kernel<<<grid, 256, shm>>>(V, out);
}